// round 1
// baseline (speedup 1.0000x reference)
#include <cuda_runtime.h>
#include <cuda_bf16.h>

#define JNT 24

__constant__ float kC0 = 0.28209479177387814f;
__constant__ float kC1 = 0.4886025119029199f;

#define SH_C0 0.28209479177387814f
#define SH_C1 0.4886025119029199f
#define C20 ( 1.0925484305920792f)
#define C21 (-1.0925484305920792f)
#define C22 ( 0.31539156525252005f)
#define C23 (-1.0925484305920792f)
#define C24 ( 0.5462742152960396f)
#define EPSF 1e-6f

__global__ __launch_bounds__(256)
void shcaster_kernel(const float* __restrict__ xyz,
                     const float* __restrict__ vdir,
                     const float* __restrict__ T,   // [J,4,4]
                     const float* __restrict__ F,   // [J,9]
                     const float* __restrict__ L,   // [J,3]
                     float* __restrict__ out,       // [2*N*3] : xyz_out then vd_out
                     int N)
{
    __shared__ float sT[JNT * 12];  // rows 0..2 of each 4x4
    __shared__ float sF[JNT * 9];
    __shared__ float sL[JNT * 3];

    const int tid = threadIdx.x;
    for (int t = tid; t < JNT * 12; t += blockDim.x)
        sT[t] = T[(t / 12) * 16 + (t % 12)];
    for (int t = tid; t < JNT * 9; t += blockDim.x)
        sF[t] = F[t];
    for (int t = tid; t < JNT * 3; t += blockDim.x)
        sL[t] = L[t];
    __syncthreads();

    const int i = blockIdx.x * blockDim.x + tid;
    if (i >= N) return;

    const float x0 = xyz[3 * i + 0];
    const float x1 = xyz[3 * i + 1];
    const float x2 = xyz[3 * i + 2];
    const float v0 = vdir[3 * i + 0];
    const float v1 = vdir[3 * i + 1];
    const float v2 = vdir[3 * i + 2];

    float wsum = 0.f;
    float s0 = 0.f, s1 = 0.f, s2 = 0.f;               // sum w * (T x)
    float m00 = 0.f, m01 = 0.f, m02 = 0.f;            // sum w * R
    float m10 = 0.f, m11 = 0.f, m12 = 0.f;
    float m20 = 0.f, m21 = 0.f, m22 = 0.f;

#pragma unroll
    for (int j = 0; j < JNT; j++) {
        const float* t = &sT[j * 12];
        const float t00 = t[0], t01 = t[1],  t02 = t[2],  t03 = t[3];
        const float t10 = t[4], t11 = t[5],  t12 = t[6],  t13 = t[7];
        const float t20 = t[8], t21 = t[9],  t22 = t[10], t23 = t[11];

        // per-joint transformed point xj = R*x + trans
        const float a0 = fmaf(t00, x0, fmaf(t01, x1, fmaf(t02, x2, t03)));
        const float a1 = fmaf(t10, x0, fmaf(t11, x1, fmaf(t12, x2, t13)));
        const float a2 = fmaf(t20, x0, fmaf(t21, x1, fmaf(t22, x2, t23)));

        // direction toward joint loc
        const float d0 = sL[j * 3 + 0] - a0;
        const float d1 = sL[j * 3 + 1] - a1;
        const float d2 = sL[j * 3 + 2] - a2;
        const float l2  = fmaf(d0, d0, fmaf(d1, d1, d2 * d2));
        const float inv = rsqrtf(l2);
        const float len = l2 * inv;
        const float ux = d0 * inv, uy = d1 * inv, uz = d2 * inv;

        // degree-2 SH dot with features
        const float* f = &sF[j * 9];
        float rad = SH_C0 * f[0];
        rad = fmaf(-SH_C1 * uy, f[1], rad);
        rad = fmaf( SH_C1 * uz, f[2], rad);
        rad = fmaf(-SH_C1 * ux, f[3], rad);
        rad = fmaf(C20 * (ux * uy), f[4], rad);
        rad = fmaf(C21 * (uy * uz), f[5], rad);
        const float q = fmaf(2.f, uz * uz, -fmaf(ux, ux, uy * uy));
        rad = fmaf(C22 * q, f[6], rad);
        rad = fmaf(C23 * (ux * uz), f[7], rad);
        rad = fmaf(C24 * fmaf(ux, ux, -(uy * uy)), f[8], rad);
        rad = fmaxf(rad + 0.5f, 0.f);

        float w = 0.f;
        if (rad >= EPSF)
            w = fmaxf(1.f - __fdividef(len, rad), 0.f);

        wsum += w;
        s0 = fmaf(w, a0, s0);
        s1 = fmaf(w, a1, s1);
        s2 = fmaf(w, a2, s2);
        m00 = fmaf(w, t00, m00); m01 = fmaf(w, t01, m01); m02 = fmaf(w, t02, m02);
        m10 = fmaf(w, t10, m10); m11 = fmaf(w, t11, m11); m12 = fmaf(w, t12, m12);
        m20 = fmaf(w, t20, m20); m21 = fmaf(w, t21, m21); m22 = fmaf(w, t22, m22);
    }

    const float c  = fmaxf(wsum, EPSF);
    const float ic = 1.0f / c;
    const bool valid = wsum > EPSF;

    // xyz_out
    const float o0 = valid ? s0 * ic : x0;
    const float o1 = valid ? s1 * ic : x1;
    const float o2 = valid ? s2 * ic : x2;

    // vd_out = (sum w R) @ viewdirs / c   (or viewdirs when invalid)
    const float e0 = fmaf(m00, v0, fmaf(m01, v1, m02 * v2)) * ic;
    const float e1 = fmaf(m10, v0, fmaf(m11, v1, m12 * v2)) * ic;
    const float e2 = fmaf(m20, v0, fmaf(m21, v1, m22 * v2)) * ic;
    const float g0 = valid ? e0 : v0;
    const float g1 = valid ? e1 : v1;
    const float g2 = valid ? e2 : v2;

    out[3 * i + 0] = o0;
    out[3 * i + 1] = o1;
    out[3 * i + 2] = o2;
    float* out2 = out + (size_t)3 * N;
    out2[3 * i + 0] = g0;
    out2[3 * i + 1] = g1;
    out2[3 * i + 2] = g2;
}

extern "C" void kernel_launch(void* const* d_in, const int* in_sizes, int n_in,
                              void* d_out, int out_size)
{
    const float* xyz  = (const float*)d_in[0];  // [B,S,3]
    const float* vdir = (const float*)d_in[1];  // [B,S,3]
    const float* T    = (const float*)d_in[2];  // [J,4,4]
    const float* F    = (const float*)d_in[3];  // [J,9]
    const float* L    = (const float*)d_in[4];  // [J,3]
    float* out        = (float*)d_out;

    const int N = in_sizes[0] / 3;              // 262144
    const int threads = 256;
    const int blocks = (N + threads - 1) / threads;
    shcaster_kernel<<<blocks, threads>>>(xyz, vdir, T, F, L, out, N);
}